// round 1
// baseline (speedup 1.0000x reference)
#include <cuda_runtime.h>
#include <cuda_bf16.h>
#include <cstdint>

#define EMBED 1024
#define HEADS 16
#define HDIM  64
#define NBATCH 2
#define SEQ   2048
#define MTOT  (NBATCH * SEQ)   // 4096

// ---------------- scratch (device globals: allocation-free) ----------------
__device__ float g_Q[NBATCH * HEADS * SEQ * HDIM];   // [N,H,L,D] 16MB
__device__ float g_K[NBATCH * HEADS * SEQ * HDIM];
__device__ float g_V[NBATCH * HEADS * SEQ * HDIM];
__device__ float g_AO[NBATCH * SEQ * EMBED];         // attention output [N,L,E]

// ============================================================================
// GEMM 1: QKV projections.  out[m,c] = sum_k x[m,k] * W[c,k]
// 128x128 block tile, BK=16, 256 threads, 8x8 per-thread micro-tile.
// Epilogue scatters into [N,H,L,D] layout.
// ============================================================================
__global__ void __launch_bounds__(256) qkv_kernel(
    const float* __restrict__ x,
    const float* __restrict__ Wq,
    const float* __restrict__ Wk,
    const float* __restrict__ Wv)
{
    __shared__ float As[16][128];
    __shared__ float Bs[16][128];

    const float* W   = (blockIdx.z == 0) ? Wq : (blockIdx.z == 1) ? Wk : Wv;
    float*       dst = (blockIdx.z == 0) ? g_Q : (blockIdx.z == 1) ? g_K : g_V;

    const int tid = threadIdx.x;
    const int tx  = tid & 15;
    const int ty  = tid >> 4;
    const int row0 = blockIdx.y * 128;
    const int col0 = blockIdx.x * 128;

    float acc[8][8];
#pragma unroll
    for (int i = 0; i < 8; i++)
#pragma unroll
        for (int j = 0; j < 8; j++) acc[i][j] = 0.f;

    for (int k0 = 0; k0 < EMBED; k0 += 16) {
#pragma unroll
        for (int t = 0; t < 2; t++) {
            int f  = tid + t * 256;          // 0..511
            int rr = f >> 2;                 // 0..127
            int kq = (f & 3) << 2;           // 0,4,8,12
            float4 av = *(const float4*)(x + (row0 + rr) * EMBED + k0 + kq);
            As[kq + 0][rr] = av.x; As[kq + 1][rr] = av.y;
            As[kq + 2][rr] = av.z; As[kq + 3][rr] = av.w;
            float4 bv = *(const float4*)(W + (col0 + rr) * EMBED + k0 + kq);
            Bs[kq + 0][rr] = bv.x; Bs[kq + 1][rr] = bv.y;
            Bs[kq + 2][rr] = bv.z; Bs[kq + 3][rr] = bv.w;
        }
        __syncthreads();

#pragma unroll
        for (int kk = 0; kk < 16; kk++) {
            float a[8], b[8];
            *(float4*)(a)     = *(const float4*)&As[kk][ty * 8];
            *(float4*)(a + 4) = *(const float4*)&As[kk][ty * 8 + 4];
            *(float4*)(b)     = *(const float4*)&Bs[kk][tx * 8];
            *(float4*)(b + 4) = *(const float4*)&Bs[kk][tx * 8 + 4];
#pragma unroll
            for (int i = 0; i < 8; i++)
#pragma unroll
                for (int j = 0; j < 8; j++) acc[i][j] = fmaf(a[i], b[j], acc[i][j]);
        }
        __syncthreads();
    }

    // scatter into [N,H,L,D]
#pragma unroll
    for (int i = 0; i < 8; i++) {
        int m = row0 + ty * 8 + i;
        int nb = m >> 11;          // m / SEQ
        int l  = m & (SEQ - 1);
#pragma unroll
        for (int jh = 0; jh < 2; jh++) {
            int c = col0 + tx * 8 + jh * 4;
            int h = c >> 6;
            int d = c & 63;
            float4 v = make_float4(acc[i][jh * 4 + 0], acc[i][jh * 4 + 1],
                                   acc[i][jh * 4 + 2], acc[i][jh * 4 + 3]);
            *(float4*)(dst + ((nb * HEADS + h) * SEQ + l) * HDIM + d) = v;
        }
    }
}

// ============================================================================
// GEMM 3: output projection. out[m,c] = sum_k AO[m,k] * Wo[c,k] + bo[c]
// ============================================================================
__global__ void __launch_bounds__(256) proj_kernel(
    const float* __restrict__ Wo,
    const float* __restrict__ bo,
    float* __restrict__ out)
{
    __shared__ float As[16][128];
    __shared__ float Bs[16][128];

    const int tid = threadIdx.x;
    const int tx  = tid & 15;
    const int ty  = tid >> 4;
    const int row0 = blockIdx.y * 128;
    const int col0 = blockIdx.x * 128;

    float acc[8][8];
#pragma unroll
    for (int i = 0; i < 8; i++)
#pragma unroll
        for (int j = 0; j < 8; j++) acc[i][j] = 0.f;

    for (int k0 = 0; k0 < EMBED; k0 += 16) {
#pragma unroll
        for (int t = 0; t < 2; t++) {
            int f  = tid + t * 256;
            int rr = f >> 2;
            int kq = (f & 3) << 2;
            float4 av = *(const float4*)(g_AO + (row0 + rr) * EMBED + k0 + kq);
            As[kq + 0][rr] = av.x; As[kq + 1][rr] = av.y;
            As[kq + 2][rr] = av.z; As[kq + 3][rr] = av.w;
            float4 bv = *(const float4*)(Wo + (col0 + rr) * EMBED + k0 + kq);
            Bs[kq + 0][rr] = bv.x; Bs[kq + 1][rr] = bv.y;
            Bs[kq + 2][rr] = bv.z; Bs[kq + 3][rr] = bv.w;
        }
        __syncthreads();

#pragma unroll
        for (int kk = 0; kk < 16; kk++) {
            float a[8], b[8];
            *(float4*)(a)     = *(const float4*)&As[kk][ty * 8];
            *(float4*)(a + 4) = *(const float4*)&As[kk][ty * 8 + 4];
            *(float4*)(b)     = *(const float4*)&Bs[kk][tx * 8];
            *(float4*)(b + 4) = *(const float4*)&Bs[kk][tx * 8 + 4];
#pragma unroll
            for (int i = 0; i < 8; i++)
#pragma unroll
                for (int j = 0; j < 8; j++) acc[i][j] = fmaf(a[i], b[j], acc[i][j]);
        }
        __syncthreads();
    }

#pragma unroll
    for (int i = 0; i < 8; i++) {
        int m = row0 + ty * 8 + i;
#pragma unroll
        for (int jh = 0; jh < 2; jh++) {
            int c = col0 + tx * 8 + jh * 4;
            float4 bb = *(const float4*)(bo + c);
            float4 v = make_float4(acc[i][jh * 4 + 0] + bb.x, acc[i][jh * 4 + 1] + bb.y,
                                   acc[i][jh * 4 + 2] + bb.z, acc[i][jh * 4 + 3] + bb.w);
            *(float4*)(out + m * EMBED + c) = v;
        }
    }
}

// ============================================================================
// GEMM 2: flash attention. One block = one (n, h, 64-query tile).
// BM=BN=64, D=64. 256 threads as 16x16, 4x4 micro-tiles.
// smem: Qs[64][68] (row-major, pre-scaled), Kts[64][68] (d-major),
//       Vs[64][68] (row-major), Ps[64][68]. All compute reads conflict-free.
// A score row r = ty*4+i is produced & consumed entirely within one warp,
// so only __syncwarp between S-GEMM and PV-GEMM.
// ============================================================================
#define AT_ST 68
#define ATT_SMEM (4 * 64 * AT_ST * (int)sizeof(float))   // 69632 B

__global__ void __launch_bounds__(256) attn_kernel()
{
    extern __shared__ float sm[];
    float* Qs  = sm;
    float* Kts = sm + 64 * AT_ST;
    float* Vs  = sm + 2 * 64 * AT_ST;
    float* Ps  = sm + 3 * 64 * AT_ST;

    const int tid = threadIdx.x;
    const int tx  = tid & 15;
    const int ty  = tid >> 4;
    const int qb  = blockIdx.x;   // query tile 0..31
    const int h   = blockIdx.y;
    const int nb  = blockIdx.z;

    const float* Qg = g_Q + ((nb * HEADS + h) * SEQ + qb * 64) * HDIM;
    const float* Kg = g_K + (nb * HEADS + h) * SEQ * HDIM;
    const float* Vg = g_V + (nb * HEADS + h) * SEQ * HDIM;

    const float scale = 1.0f / 32.0f;   // 1/sqrt(EMBED)

    // load Q tile, pre-scaled
#pragma unroll
    for (int t = 0; t < 4; t++) {
        int f  = tid + t * 256;         // 0..1023
        int r  = f >> 4;
        int dq = (f & 15) << 2;
        float4 v = *(const float4*)(Qg + r * HDIM + dq);
        v.x *= scale; v.y *= scale; v.z *= scale; v.w *= scale;
        *(float4*)(Qs + r * AT_ST + dq) = v;
    }

    float mi[4], li[4], acc[4][4];
#pragma unroll
    for (int i = 0; i < 4; i++) {
        mi[i] = -1e30f; li[i] = 0.f;
#pragma unroll
        for (int j = 0; j < 4; j++) acc[i][j] = 0.f;
    }

    for (int kb = 0; kb < SEQ / 64; kb++) {
        __syncthreads();   // previous tile's consumers done
        const float* Kt = Kg + kb * 64 * HDIM;
        const float* Vt = Vg + kb * 64 * HDIM;
#pragma unroll
        for (int t = 0; t < 4; t++) {
            int f  = tid + t * 256;
            int c  = f >> 4;
            int dq = (f & 15) << 2;
            float4 kv = *(const float4*)(Kt + c * HDIM + dq);
            Kts[(dq + 0) * AT_ST + c] = kv.x;
            Kts[(dq + 1) * AT_ST + c] = kv.y;
            Kts[(dq + 2) * AT_ST + c] = kv.z;
            Kts[(dq + 3) * AT_ST + c] = kv.w;
            float4 vv = *(const float4*)(Vt + c * HDIM + dq);
            *(float4*)(Vs + c * AT_ST + dq) = vv;
        }
        __syncthreads();

        // S = Q @ K^T (pre-scaled)
        float s[4][4];
#pragma unroll
        for (int i = 0; i < 4; i++)
#pragma unroll
            for (int j = 0; j < 4; j++) s[i][j] = 0.f;

#pragma unroll 8
        for (int d = 0; d < HDIM; d++) {
            float qv[4], kv[4];
#pragma unroll
            for (int i = 0; i < 4; i++) qv[i] = Qs[(ty * 4 + i) * AT_ST + d];
#pragma unroll
            for (int j = 0; j < 4; j++) kv[j] = Kts[d * AT_ST + tx * 4 + j];
#pragma unroll
            for (int i = 0; i < 4; i++)
#pragma unroll
                for (int j = 0; j < 4; j++) s[i][j] = fmaf(qv[i], kv[j], s[i][j]);
        }

        // online softmax; rows reduce across the 16 tx lanes (same warp half)
#pragma unroll
        for (int i = 0; i < 4; i++) {
            float rm = fmaxf(fmaxf(s[i][0], s[i][1]), fmaxf(s[i][2], s[i][3]));
#pragma unroll
            for (int o = 8; o > 0; o >>= 1)
                rm = fmaxf(rm, __shfl_xor_sync(0xffffffffu, rm, o));
            float mnew = fmaxf(mi[i], rm);
            float corr = __expf(mi[i] - mnew);
            float rs = 0.f;
#pragma unroll
            for (int j = 0; j < 4; j++) {
                float p = __expf(s[i][j] - mnew);
                Ps[(ty * 4 + i) * AT_ST + tx * 4 + j] = p;
                rs += p;
            }
#pragma unroll
            for (int o = 8; o > 0; o >>= 1)
                rs += __shfl_xor_sync(0xffffffffu, rs, o);
            li[i] = li[i] * corr + rs;
            mi[i] = mnew;
#pragma unroll
            for (int j = 0; j < 4; j++) acc[i][j] *= corr;
        }
        __syncwarp();   // P row is warp-local: no block sync needed

        // O += P @ V
#pragma unroll 8
        for (int jj = 0; jj < 64; jj++) {
            float pv[4], vv[4];
#pragma unroll
            for (int i = 0; i < 4; i++) pv[i] = Ps[(ty * 4 + i) * AT_ST + jj];
#pragma unroll
            for (int j = 0; j < 4; j++) vv[j] = Vs[jj * AT_ST + tx * 4 + j];
#pragma unroll
            for (int i = 0; i < 4; i++)
#pragma unroll
                for (int j = 0; j < 4; j++) acc[i][j] = fmaf(pv[i], vv[j], acc[i][j]);
        }
        __syncwarp();   // done reading Ps before next-iter overwrite
    }

    // epilogue: write [N,L,E]
    float* Og = g_AO + (nb * SEQ + qb * 64) * EMBED + h * HDIM;
#pragma unroll
    for (int i = 0; i < 4; i++) {
        float inv = 1.f / li[i];
        float4 o = make_float4(acc[i][0] * inv, acc[i][1] * inv,
                               acc[i][2] * inv, acc[i][3] * inv);
        *(float4*)(Og + (ty * 4 + i) * EMBED + tx * 4) = o;
    }
}

// ============================================================================
extern "C" void kernel_launch(void* const* d_in, const int* in_sizes, int n_in,
                              void* d_out, int out_size)
{
    const float* x  = (const float*)d_in[0];
    const float* Wq = (const float*)d_in[1];
    const float* Wk = (const float*)d_in[2];
    const float* Wv = (const float*)d_in[3];
    const float* Wo = (const float*)d_in[4];
    const float* bo = (const float*)d_in[5];
    float* out = (float*)d_out;

    cudaFuncSetAttribute(attn_kernel,
                         cudaFuncAttributeMaxDynamicSharedMemorySize, ATT_SMEM);

    dim3 g1(EMBED / 128, MTOT / 128, 3);
    qkv_kernel<<<g1, 256>>>(x, Wq, Wk, Wv);

    dim3 g2(SEQ / 64, HEADS, NBATCH);
    attn_kernel<<<g2, 256, ATT_SMEM>>>();

    dim3 g3(EMBED / 128, MTOT / 128);
    proj_kernel<<<g3, 256>>>(Wo, bo, out);
}

// round 3
// speedup vs baseline: 3.3028x; 3.3028x over previous
#include <cuda_runtime.h>
#include <cstdint>

#define EMBED 1024
#define HEADS 16
#define HDIM  64
#define NBATCH 2
#define SEQ   2048
#define MTOT  (NBATCH * SEQ)   // 4096

// ---------------- scratch (device globals: allocation-free) ----------------
__device__ float g_Q[NBATCH * HEADS * SEQ * HDIM];
__device__ float g_K[NBATCH * HEADS * SEQ * HDIM];
__device__ float g_V[NBATCH * HEADS * SEQ * HDIM];
__device__ float g_AO[MTOT * EMBED];
__device__ float g_xc[MTOT * EMBED];       // tf32-rounded x
__device__ float g_wq[EMBED * EMBED];
__device__ float g_wk[EMBED * EMBED];
__device__ float g_wv[EMBED * EMBED];
__device__ float g_wo[EMBED * EMBED];

// ======================= helpers (arch-neutral PTX) =========================
__device__ __forceinline__ float tf32r(float x) {
    uint32_t u;
    asm("cvt.rna.tf32.f32 %0, %1;" : "=r"(u) : "f"(x));
    return __uint_as_float(u);
}
__device__ __forceinline__ uint32_t smem_u32(const void* p) {
    uint32_t a;
    asm("{ .reg .u64 t; cvta.to.shared.u64 t, %1; cvt.u32.u64 %0, t; }"
        : "=r"(a) : "l"(p));
    return a;
}
__device__ __forceinline__ void cp_async16(uint32_t s, const void* g) {
    asm volatile("cp.async.cg.shared.global [%0], [%1], 16;" :: "r"(s), "l"(g));
}
#define CP_COMMIT() asm volatile("cp.async.commit_group;" ::: "memory")
#define CP_WAIT1()  asm volatile("cp.async.wait_group 1;" ::: "memory")

__device__ __forceinline__ void ldm_x4(uint32_t (&r)[4], uint32_t a) {
    asm volatile("ldmatrix.sync.aligned.m8n8.x4.shared.b16 {%0,%1,%2,%3}, [%4];"
                 : "=r"(r[0]), "=r"(r[1]), "=r"(r[2]), "=r"(r[3]) : "r"(a));
}
__device__ __forceinline__ void ldm_x2(uint32_t (&r)[2], uint32_t a) {
    asm volatile("ldmatrix.sync.aligned.m8n8.x2.shared.b16 {%0,%1}, [%2];"
                 : "=r"(r[0]), "=r"(r[1]) : "r"(a));
}
__device__ __forceinline__ void mma_tf32(float (&d)[4], const uint32_t (&a)[4],
                                         const uint32_t (&b)[2]) {
    asm volatile("mma.sync.aligned.m16n8k8.row.col.f32.tf32.tf32.f32 "
                 "{%0,%1,%2,%3}, {%4,%5,%6,%7}, {%8,%9}, {%0,%1,%2,%3};"
                 : "+f"(d[0]), "+f"(d[1]), "+f"(d[2]), "+f"(d[3])
                 : "r"(a[0]), "r"(a[1]), "r"(a[2]), "r"(a[3]),
                   "r"(b[0]), "r"(b[1]));
}

// ======================= prep: tf32-round x and weights =====================
__global__ void __launch_bounds__(256) prep_cvt(
    const float* __restrict__ x,  const float* __restrict__ wq,
    const float* __restrict__ wk, const float* __restrict__ wv,
    const float* __restrict__ wo)
{
    int t = blockIdx.y;
    const float* src = (t == 0) ? x : (t == 1) ? wq : (t == 2) ? wk
                     : (t == 3) ? wv : wo;
    float* dst = (t == 0) ? g_xc : (t == 1) ? g_wq : (t == 2) ? g_wk
               : (t == 3) ? g_wv : g_wo;
    int n4 = ((t == 0) ? MTOT * EMBED : EMBED * EMBED) / 4;
    for (int i = blockIdx.x * blockDim.x + threadIdx.x; i < n4;
         i += gridDim.x * blockDim.x) {
        float4 v = ((const float4*)src)[i];
        v.x = tf32r(v.x); v.y = tf32r(v.y); v.z = tf32r(v.z); v.w = tf32r(v.w);
        ((float4*)dst)[i] = v;
    }
}

// ======================= tf32 mma GEMM core (128x128xK) =====================
// smem: As[128][36], Bs[128][36] per buffer; layout [A0][B0][A1][B1].
#define GA_BYTES 18432                // 128*36*4
#define GBUF     36864                // A+B per stage
#define G_SMEM   73728

__device__ __forceinline__ void g_load_tile(const float* __restrict__ g,
                                            uint32_t s, int k0, int tid) {
#pragma unroll
    for (int t = 0; t < 4; t++) {
        int c   = tid + t * 256;      // 0..1023
        int row = c >> 3;
        int ch  = c & 7;
        cp_async16(s + (uint32_t)(row * 36 + ch * 4) * 4u,
                   g + row * EMBED + k0 + ch * 4);
    }
}

__device__ __forceinline__ void gemm_core(const float* __restrict__ Ag,
                                          const float* __restrict__ Bg,
                                          uint32_t sbase, int tid,
                                          float acc[4][4][4]) {
    const int w = tid >> 5, l = tid & 31;
    const int wm = (w >> 2) * 64, wn = (w & 3) * 32;
    const uint32_t rowA = (uint32_t)(wm + ((l >> 3) & 1) * 8 + (l & 7));
    const uint32_t colA = (uint32_t)((l >> 4) * 4);
    const uint32_t rowB = (uint32_t)(wn + (l & 7));
    const uint32_t colB = (uint32_t)(((l >> 3) & 1) * 4);

    uint32_t sA = sbase, sB = sbase + GA_BYTES;
    g_load_tile(Ag, sA, 0, tid);  g_load_tile(Bg, sB, 0, tid);  CP_COMMIT();
    g_load_tile(Ag, sA + GBUF, 32, tid); g_load_tile(Bg, sB + GBUF, 32, tid);
    CP_COMMIT();

    for (int i = 0; i < 32; i++) {
        CP_WAIT1();
        __syncthreads();
        uint32_t bo = (uint32_t)(i & 1) * GBUF;
        uint32_t ab = sA + bo, bb = sB + bo;
#pragma unroll
        for (int ks = 0; ks < 4; ks++) {
            int kk = ks * 8;
            uint32_t a[4][4];
#pragma unroll
            for (int mt = 0; mt < 4; mt++)
                ldm_x4(a[mt], ab + ((rowA + mt * 16) * 36 + kk + colA) * 4);
            uint32_t b[4][2];
#pragma unroll
            for (int nt = 0; nt < 4; nt++)
                ldm_x2(b[nt], bb + ((rowB + nt * 8) * 36 + kk + colB) * 4);
#pragma unroll
            for (int mt = 0; mt < 4; mt++)
#pragma unroll
                for (int nt = 0; nt < 4; nt++)
                    mma_tf32(acc[mt][nt], a[mt], b[nt]);
        }
        __syncthreads();
        if (i + 2 < 32) {
            g_load_tile(Ag, sA + bo, (i + 2) * 32, tid);
            g_load_tile(Bg, sB + bo, (i + 2) * 32, tid);
        }
        CP_COMMIT();
    }
}

// ---------------------------- QKV -------------------------------------------
__global__ void __launch_bounds__(256) qkv_tc()
{
    extern __shared__ char dyn[];
    uint32_t sbase = smem_u32(dyn);
    const int tid = threadIdx.x, w = tid >> 5, l = tid & 31;
    const int row0 = blockIdx.y * 128, col0 = blockIdx.x * 128;
    const float* W = (blockIdx.z == 0) ? g_wq : (blockIdx.z == 1) ? g_wk : g_wv;
    float*     dst = (blockIdx.z == 0) ? g_Q  : (blockIdx.z == 1) ? g_K  : g_V;

    float acc[4][4][4] = {};
    gemm_core(g_xc + row0 * EMBED, W + col0 * EMBED, sbase, tid, acc);

    const int wm = (w >> 2) * 64, wn = (w & 3) * 32;
#pragma unroll
    for (int mt = 0; mt < 4; mt++) {
        int r  = row0 + wm + mt * 16 + (l >> 2);
        int nb = r >> 11;
        int ll = r & (SEQ - 1);
#pragma unroll
        for (int nt = 0; nt < 4; nt++) {
            int cc = col0 + wn + nt * 8 + 2 * (l & 3);
            int h  = cc >> 6, d = cc & 63;
            float* p = dst + ((nb * HEADS + h) * SEQ + ll) * HDIM + d;
            *(float2*)p = make_float2(tf32r(acc[mt][nt][0]), tf32r(acc[mt][nt][1]));
            *(float2*)(p + 8 * HDIM) =
                make_float2(tf32r(acc[mt][nt][2]), tf32r(acc[mt][nt][3]));
        }
    }
}

// ---------------------------- proj ------------------------------------------
__global__ void __launch_bounds__(256) proj_tc(
    const float* __restrict__ bo, float* __restrict__ out)
{
    extern __shared__ char dyn[];
    uint32_t sbase = smem_u32(dyn);
    const int tid = threadIdx.x, w = tid >> 5, l = tid & 31;
    const int row0 = blockIdx.y * 128, col0 = blockIdx.x * 128;

    float acc[4][4][4] = {};
    gemm_core(g_AO + row0 * EMBED, g_wo + col0 * EMBED, sbase, tid, acc);

    const int wm = (w >> 2) * 64, wn = (w & 3) * 32;
#pragma unroll
    for (int mt = 0; mt < 4; mt++) {
        int r = row0 + wm + mt * 16 + (l >> 2);
#pragma unroll
        for (int nt = 0; nt < 4; nt++) {
            int cc = col0 + wn + nt * 8 + 2 * (l & 3);
            float b0 = bo[cc], b1 = bo[cc + 1];
            *(float2*)(out + r * EMBED + cc) =
                make_float2(acc[mt][nt][0] + b0, acc[mt][nt][1] + b1);
            *(float2*)(out + (r + 8) * EMBED + cc) =
                make_float2(acc[mt][nt][2] + b0, acc[mt][nt][3] + b1);
        }
    }
}

// ======================= flash attention, tf32 mma ==========================
// CTA per (qtile128, head, batch). 8 warps, warp = 16 q rows.
// Qs[128][68], Ps[128][68], Ks 2x[64][68], Vs 2x[64][72].
#define A_OFF_P 34816
#define A_OFF_K 69632
#define A_KBUF  17408
#define A_OFF_V 104448
#define A_VBUF  18432
#define A_SMEM  141312

__device__ __forceinline__ void load_kv(const float* __restrict__ Kg,
                                        const float* __restrict__ Vg,
                                        uint32_t kbuf, uint32_t vbuf,
                                        int kv0, int tid) {
#pragma unroll
    for (int t = 0; t < 4; t++) {
        int c = tid + t * 256;
        int r = c >> 4, ch = c & 15;
        cp_async16(kbuf + (uint32_t)(r * 68 + ch * 4) * 4u,
                   Kg + (kv0 + r) * HDIM + ch * 4);
    }
#pragma unroll
    for (int t = 0; t < 4; t++) {
        int c = tid + t * 256;
        int r = c >> 4, ch = c & 15;
        cp_async16(vbuf + (uint32_t)(r * 72 + ch * 4) * 4u,
                   Vg + (kv0 + r) * HDIM + ch * 4);
    }
}

__global__ void __launch_bounds__(256) attn_tc()
{
    extern __shared__ char dyn[];
    uint32_t sb = smem_u32(dyn);
    float* smf = (float*)dyn;
    const int tid = threadIdx.x, w = tid >> 5, l = tid & 31;
    const int qb = blockIdx.x, h = blockIdx.y, nb = blockIdx.z;

    const float* Qg = g_Q + ((nb * HEADS + h) * SEQ + qb * 128) * HDIM;
    const float* Kg = g_K + (nb * HEADS + h) * SEQ * HDIM;
    const float* Vg = g_V + (nb * HEADS + h) * SEQ * HDIM;

    uint32_t sQ = sb, sP = sb + A_OFF_P, sK = sb + A_OFF_K, sV = sb + A_OFF_V;

    load_kv(Kg, Vg, sK, sV, 0, tid);  CP_COMMIT();
    load_kv(Kg, Vg, sK + A_KBUF, sV + A_VBUF, 64, tid);  CP_COMMIT();

    // Q load, scaled by 1/sqrt(EMBED)=1/32 (exact power of 2)
#pragma unroll
    for (int t = 0; t < 8; t++) {
        int c = tid + t * 256;        // 0..2047
        int r = c >> 4, ch = c & 15;
        float4 v = *(const float4*)(Qg + r * HDIM + ch * 4);
        v.x *= 0.03125f; v.y *= 0.03125f; v.z *= 0.03125f; v.w *= 0.03125f;
        *(float4*)(smf + r * 68 + ch * 4) = v;
    }

    const int wm = w * 16;
    const uint32_t rowA = (uint32_t)(wm + ((l >> 3) & 1) * 8 + (l & 7));
    const uint32_t colA = (uint32_t)((l >> 4) * 4);
    const uint32_t rowBk = (uint32_t)(l & 7);
    const uint32_t colBk = (uint32_t)(((l >> 3) & 1) * 4);

    float o[8][4] = {};
    float mi0 = -1e30f, mi1 = -1e30f, li0 = 0.f, li1 = 0.f;

    for (int it = 0; it < SEQ / 64; it++) {
        CP_WAIT1();
        __syncthreads();
        uint32_t kb = sK + (uint32_t)(it & 1) * A_KBUF;
        const float* Vp = smf + (A_OFF_V >> 2) + (it & 1) * (A_VBUF >> 2);

        // ---- S = Q @ K^T ----
        float sv[8][4] = {};
#pragma unroll
        for (int ks = 0; ks < 8; ks++) {
            int kk = ks * 8;
            uint32_t a[4];
            ldm_x4(a, sQ + (rowA * 68 + kk + colA) * 4);
#pragma unroll
            for (int nt = 0; nt < 8; nt++) {
                uint32_t b[2];
                ldm_x2(b, kb + ((nt * 8 + rowBk) * 68 + kk + colBk) * 4);
                mma_tf32(sv[nt], a, b);
            }
        }

        // ---- online softmax (rows r0=wm+(l>>2), r1=r0+8) ----
        float rm0 = -1e30f, rm1 = -1e30f;
#pragma unroll
        for (int nt = 0; nt < 8; nt++) {
            rm0 = fmaxf(rm0, fmaxf(sv[nt][0], sv[nt][1]));
            rm1 = fmaxf(rm1, fmaxf(sv[nt][2], sv[nt][3]));
        }
#pragma unroll
        for (int off = 1; off <= 2; off <<= 1) {
            rm0 = fmaxf(rm0, __shfl_xor_sync(0xffffffffu, rm0, off));
            rm1 = fmaxf(rm1, __shfl_xor_sync(0xffffffffu, rm1, off));
        }
        float mn0 = fmaxf(mi0, rm0), mn1 = fmaxf(mi1, rm1);
        float c0 = __expf(mi0 - mn0), c1 = __expf(mi1 - mn1);
        float rs0 = 0.f, rs1 = 0.f;
        float* Pp = smf + (A_OFF_P >> 2);
        int pr0 = wm + (l >> 2);
#pragma unroll
        for (int nt = 0; nt < 8; nt++) {
            float p0 = tf32r(__expf(sv[nt][0] - mn0));
            float p1 = tf32r(__expf(sv[nt][1] - mn0));
            float p2 = tf32r(__expf(sv[nt][2] - mn1));
            float p3 = tf32r(__expf(sv[nt][3] - mn1));
            rs0 += p0 + p1;  rs1 += p2 + p3;
            int cc = nt * 8 + 2 * (l & 3);
            *(float2*)(Pp + pr0 * 68 + cc)       = make_float2(p0, p1);
            *(float2*)(Pp + (pr0 + 8) * 68 + cc) = make_float2(p2, p3);
        }
#pragma unroll
        for (int off = 1; off <= 2; off <<= 1) {
            rs0 += __shfl_xor_sync(0xffffffffu, rs0, off);
            rs1 += __shfl_xor_sync(0xffffffffu, rs1, off);
        }
        li0 = li0 * c0 + rs0;  li1 = li1 * c1 + rs1;
        mi0 = mn0;  mi1 = mn1;
#pragma unroll
        for (int dt = 0; dt < 8; dt++) {
            o[dt][0] *= c0; o[dt][1] *= c0; o[dt][2] *= c1; o[dt][3] *= c1;
        }
        __syncwarp();

        // ---- O += P @ V ----
#pragma unroll
        for (int ks = 0; ks < 8; ks++) {
            int kk = ks * 8;
            uint32_t a[4];
            ldm_x4(a, sP + (rowA * 68 + kk + colA) * 4);
#pragma unroll
            for (int dt = 0; dt < 8; dt++) {
                uint32_t b[2];
                b[0] = __float_as_uint(Vp[(kk + (l & 3)) * 72 + dt * 8 + (l >> 2)]);
                b[1] = __float_as_uint(Vp[(kk + (l & 3) + 4) * 72 + dt * 8 + (l >> 2)]);
                mma_tf32(o[dt], a, b);
            }
        }
        __syncthreads();
        if (it + 2 < SEQ / 64)
            load_kv(Kg, Vg, sK + (uint32_t)(it & 1) * A_KBUF,
                    sV + (uint32_t)(it & 1) * A_VBUF, (it + 2) * 64, tid);
        CP_COMMIT();
    }

    // epilogue -> g_AO [N,L,E], tf32-rounded (it feeds the tf32 proj GEMM)
    float inv0 = 1.f / li0, inv1 = 1.f / li1;
    int r0 = qb * 128 + wm + (l >> 2);
    float* Og = g_AO + (nb * SEQ + r0) * EMBED + h * HDIM;
#pragma unroll
    for (int dt = 0; dt < 8; dt++) {
        int cc = dt * 8 + 2 * (l & 3);
        *(float2*)(Og + cc) =
            make_float2(tf32r(o[dt][0] * inv0), tf32r(o[dt][1] * inv0));
        *(float2*)(Og + 8 * EMBED + cc) =
            make_float2(tf32r(o[dt][2] * inv1), tf32r(o[dt][3] * inv1));
    }
}

// ============================================================================
extern "C" void kernel_launch(void* const* d_in, const int* in_sizes, int n_in,
                              void* d_out, int out_size)
{
    const float* x  = (const float*)d_in[0];
    const float* Wq = (const float*)d_in[1];
    const float* Wk = (const float*)d_in[2];
    const float* Wv = (const float*)d_in[3];
    const float* Wo = (const float*)d_in[4];
    const float* bo = (const float*)d_in[5];
    float* out = (float*)d_out;

    cudaFuncSetAttribute(qkv_tc,  cudaFuncAttributeMaxDynamicSharedMemorySize, G_SMEM);
    cudaFuncSetAttribute(proj_tc, cudaFuncAttributeMaxDynamicSharedMemorySize, G_SMEM);
    cudaFuncSetAttribute(attn_tc, cudaFuncAttributeMaxDynamicSharedMemorySize, A_SMEM);

    dim3 gp(512, 5);
    prep_cvt<<<gp, 256>>>(x, Wq, Wk, Wv, Wo);

    dim3 g1(EMBED / 128, MTOT / 128, 3);
    qkv_tc<<<g1, 256, G_SMEM>>>();

    dim3 g2(SEQ / 128, HEADS, NBATCH);
    attn_tc<<<g2, 256, A_SMEM>>>();

    dim3 g3(EMBED / 128, MTOT / 128);
    proj_tc<<<g3, 256, G_SMEM>>>(bo, out);
}

// round 4
// speedup vs baseline: 3.3388x; 1.0109x over previous
#include <cuda_runtime.h>
#include <cstdint>

#define EMBED 1024
#define HEADS 16
#define HDIM  64
#define NBATCH 2
#define SEQ   2048
#define MTOT  (NBATCH * SEQ)   // 4096

// ---------------- scratch (device globals: allocation-free) ----------------
__device__ float g_Q[NBATCH * HEADS * SEQ * HDIM];   // [N,H,L,D]
__device__ float g_K[NBATCH * HEADS * SEQ * HDIM];   // [N,H,L,D]
__device__ float g_V[NBATCH * HEADS * SEQ * HDIM];   // [N,H,D,L]  (transposed!)
__device__ float g_AO[MTOT * EMBED];
__device__ float g_xc[MTOT * EMBED];
__device__ float g_wq[EMBED * EMBED];
__device__ float g_wk[EMBED * EMBED];
__device__ float g_wv[EMBED * EMBED];
__device__ float g_wo[EMBED * EMBED];

// ======================= helpers (arch-neutral PTX) =========================
__device__ __forceinline__ float tf32r(float x) {
    uint32_t u;
    asm("cvt.rna.tf32.f32 %0, %1;" : "=r"(u) : "f"(x));
    return __uint_as_float(u);
}
__device__ __forceinline__ float fexp2(float x) {
    float y;
    asm("ex2.approx.ftz.f32 %0, %1;" : "=f"(y) : "f"(x));
    return y;
}
__device__ __forceinline__ uint32_t smem_u32(const void* p) {
    uint32_t a;
    asm("{ .reg .u64 t; cvta.to.shared.u64 t, %1; cvt.u32.u64 %0, t; }"
        : "=r"(a) : "l"(p));
    return a;
}
__device__ __forceinline__ void cp_async16(uint32_t s, const void* g) {
    asm volatile("cp.async.cg.shared.global [%0], [%1], 16;" :: "r"(s), "l"(g));
}
#define CP_COMMIT() asm volatile("cp.async.commit_group;" ::: "memory")
#define CP_WAIT1()  asm volatile("cp.async.wait_group 1;" ::: "memory")

__device__ __forceinline__ void ldm_x4(uint32_t (&r)[4], uint32_t a) {
    asm volatile("ldmatrix.sync.aligned.m8n8.x4.shared.b16 {%0,%1,%2,%3}, [%4];"
                 : "=r"(r[0]), "=r"(r[1]), "=r"(r[2]), "=r"(r[3]) : "r"(a));
}
__device__ __forceinline__ void ldm_x2(uint32_t (&r)[2], uint32_t a) {
    asm volatile("ldmatrix.sync.aligned.m8n8.x2.shared.b16 {%0,%1}, [%2];"
                 : "=r"(r[0]), "=r"(r[1]) : "r"(a));
}
__device__ __forceinline__ void mma_tf32(float (&d)[4], const uint32_t (&a)[4],
                                         const uint32_t (&b)[2]) {
    asm volatile("mma.sync.aligned.m16n8k8.row.col.f32.tf32.tf32.f32 "
                 "{%0,%1,%2,%3}, {%4,%5,%6,%7}, {%8,%9}, {%0,%1,%2,%3};"
                 : "+f"(d[0]), "+f"(d[1]), "+f"(d[2]), "+f"(d[3])
                 : "r"(a[0]), "r"(a[1]), "r"(a[2]), "r"(a[3]),
                   "r"(b[0]), "r"(b[1]));
}

// ======================= prep: tf32-round x and weights =====================
__global__ void __launch_bounds__(256) prep_cvt(
    const float* __restrict__ x,  const float* __restrict__ wq,
    const float* __restrict__ wk, const float* __restrict__ wv,
    const float* __restrict__ wo)
{
    int t = blockIdx.y;
    const float* src = (t == 0) ? x : (t == 1) ? wq : (t == 2) ? wk
                     : (t == 3) ? wv : wo;
    float* dst = (t == 0) ? g_xc : (t == 1) ? g_wq : (t == 2) ? g_wk
               : (t == 3) ? g_wv : g_wo;
    int n4 = ((t == 0) ? MTOT * EMBED : EMBED * EMBED) / 4;
    for (int i = blockIdx.x * blockDim.x + threadIdx.x; i < n4;
         i += gridDim.x * blockDim.x) {
        float4 v = ((const float4*)src)[i];
        v.x = tf32r(v.x); v.y = tf32r(v.y); v.z = tf32r(v.z); v.w = tf32r(v.w);
        ((float4*)dst)[i] = v;
    }
}

// ======================= tf32 mma GEMM core (128x128xK) =====================
// 3-stage cp.async pipeline, single __syncthreads per iter.
#define GA_BYTES 18432                // 128*36*4
#define GBUF     36864                // A+B per stage
#define G_SMEM   110592               // 3 stages

__device__ __forceinline__ void g_load_tile(const float* __restrict__ g,
                                            uint32_t s, int k0, int tid) {
#pragma unroll
    for (int t = 0; t < 4; t++) {
        int c   = tid + t * 256;
        int row = c >> 3;
        int ch  = c & 7;
        cp_async16(s + (uint32_t)(row * 36 + ch * 4) * 4u,
                   g + row * EMBED + k0 + ch * 4);
    }
}

__device__ __forceinline__ void gemm_core(const float* __restrict__ Ag,
                                          const float* __restrict__ Bg,
                                          uint32_t sbase, int tid,
                                          float acc[4][4][4]) {
    const int w = tid >> 5, l = tid & 31;
    const int wm = (w >> 2) * 64, wn = (w & 3) * 32;
    const uint32_t rowA = (uint32_t)(wm + ((l >> 3) & 1) * 8 + (l & 7));
    const uint32_t colA = (uint32_t)((l >> 4) * 4);
    const uint32_t rowB = (uint32_t)(wn + (l & 7));
    const uint32_t colB = (uint32_t)(((l >> 3) & 1) * 4);

    uint32_t sA = sbase, sB = sbase + GA_BYTES;
    g_load_tile(Ag, sA, 0, tid);  g_load_tile(Bg, sB, 0, tid);  CP_COMMIT();
    g_load_tile(Ag, sA + GBUF, 32, tid); g_load_tile(Bg, sB + GBUF, 32, tid);
    CP_COMMIT();

    for (int i = 0; i < 32; i++) {
        CP_WAIT1();            // stage i landed (stage i+1 may be in flight)
        __syncthreads();       // publish fills; iter i-1 reads are done
        if (i + 2 < 32) {
            uint32_t po = (uint32_t)((i + 2) % 3) * GBUF;   // = (i-1)%3: free
            g_load_tile(Ag, sA + po, (i + 2) * 32, tid);
            g_load_tile(Bg, sB + po, (i + 2) * 32, tid);
        }
        CP_COMMIT();
        uint32_t bo = (uint32_t)(i % 3) * GBUF;
        uint32_t ab = sA + bo, bb = sB + bo;
#pragma unroll
        for (int ks = 0; ks < 4; ks++) {
            int kk = ks * 8;
            uint32_t a[4][4];
#pragma unroll
            for (int mt = 0; mt < 4; mt++)
                ldm_x4(a[mt], ab + ((rowA + mt * 16) * 36 + kk + colA) * 4);
            uint32_t b[4][2];
#pragma unroll
            for (int nt = 0; nt < 4; nt++)
                ldm_x2(b[nt], bb + ((rowB + nt * 8) * 36 + kk + colB) * 4);
#pragma unroll
            for (int mt = 0; mt < 4; mt++)
#pragma unroll
                for (int nt = 0; nt < 4; nt++)
                    mma_tf32(acc[mt][nt], a[mt], b[nt]);
        }
    }
}

// ---------------------------- QKV -------------------------------------------
__global__ void __launch_bounds__(256) qkv_tc()
{
    extern __shared__ char dyn[];
    uint32_t sbase = smem_u32(dyn);
    const int tid = threadIdx.x, w = tid >> 5, l = tid & 31;
    const int row0 = blockIdx.y * 128, col0 = blockIdx.x * 128;
    const float* W = (blockIdx.z == 0) ? g_wq : (blockIdx.z == 1) ? g_wk : g_wv;

    float acc[4][4][4] = {};
    gemm_core(g_xc + row0 * EMBED, W + col0 * EMBED, sbase, tid, acc);

    const int wm = (w >> 2) * 64, wn = (w & 3) * 32;
    const int nb = row0 >> 11;

    if (blockIdx.z < 2) {
        float* dst = (blockIdx.z == 0) ? g_Q : g_K;
#pragma unroll
        for (int mt = 0; mt < 4; mt++) {
            int r  = row0 + wm + mt * 16 + (l >> 2);
            int ll = r & (SEQ - 1);
#pragma unroll
            for (int nt = 0; nt < 4; nt++) {
                int cc = col0 + wn + nt * 8 + 2 * (l & 3);
                int h  = cc >> 6, d = cc & 63;
                float* p = dst + ((nb * HEADS + h) * SEQ + ll) * HDIM + d;
                *(float2*)p = make_float2(tf32r(acc[mt][nt][0]), tf32r(acc[mt][nt][1]));
                *(float2*)(p + 8 * HDIM) =
                    make_float2(tf32r(acc[mt][nt][2]), tf32r(acc[mt][nt][3]));
            }
        }
    } else {
        // V: transpose in smem -> g_V [N,H,D,L]
        float* ts = (float*)dyn;              // [128 cc][132]
        __syncthreads();                      // mainloop smem reads done
#pragma unroll
        for (int mt = 0; mt < 4; mt++) {
            int r = wm + mt * 16 + (l >> 2);  // local seq row
#pragma unroll
            for (int nt = 0; nt < 4; nt++) {
                int cc = wn + nt * 8 + 2 * (l & 3);
                ts[cc * 132 + r]             = tf32r(acc[mt][nt][0]);
                ts[(cc + 1) * 132 + r]       = tf32r(acc[mt][nt][1]);
                ts[cc * 132 + r + 8]         = tf32r(acc[mt][nt][2]);
                ts[(cc + 1) * 132 + r + 8]   = tf32r(acc[mt][nt][3]);
            }
        }
        __syncthreads();
        int l0base = row0 & (SEQ - 1);
#pragma unroll
        for (int q = 0; q < 16; q++) {
            int e  = q * 256 + tid;           // 0..4095
            int cc = e >> 5;                  // 0..127
            int ls = e & 31;
            float4 v = *(const float4*)&ts[cc * 132 + ls * 4];
            int gc = col0 + cc;
            int h = gc >> 6, d = gc & 63;
            *(float4*)(g_V + ((nb * HEADS + h) * HDIM + d) * SEQ + l0base + ls * 4) = v;
        }
    }
}

// ---------------------------- proj ------------------------------------------
__global__ void __launch_bounds__(256) proj_tc(
    const float* __restrict__ bo, float* __restrict__ out)
{
    extern __shared__ char dyn[];
    uint32_t sbase = smem_u32(dyn);
    const int tid = threadIdx.x, w = tid >> 5, l = tid & 31;
    const int row0 = blockIdx.y * 128, col0 = blockIdx.x * 128;

    float acc[4][4][4] = {};
    gemm_core(g_AO + row0 * EMBED, g_wo + col0 * EMBED, sbase, tid, acc);

    const int wm = (w >> 2) * 64, wn = (w & 3) * 32;
#pragma unroll
    for (int mt = 0; mt < 4; mt++) {
        int r = row0 + wm + mt * 16 + (l >> 2);
#pragma unroll
        for (int nt = 0; nt < 4; nt++) {
            int cc = col0 + wn + nt * 8 + 2 * (l & 3);
            float b0 = bo[cc], b1 = bo[cc + 1];
            *(float2*)(out + r * EMBED + cc) =
                make_float2(acc[mt][nt][0] + b0, acc[mt][nt][1] + b1);
            *(float2*)(out + (r + 8) * EMBED + cc) =
                make_float2(acc[mt][nt][2] + b0, acc[mt][nt][3] + b1);
        }
    }
}

// ======================= flash attention, tf32 mma ==========================
// CTA per (qtile128, head, batch). 8 warps, warp = 16 q rows.
// Qs[128][68], Ps[128][68], K 3x[64][68], V^T 3x[64][68]. 3-stage, 1 sync/iter.
#define A_OFF_P 34816
#define A_OFF_K 69632
#define A_KBUF  17408
#define A_OFF_V (A_OFF_K + 3 * A_KBUF)   // 121856
#define A_SMEM  (A_OFF_V + 3 * A_KBUF)   // 174080

__device__ __forceinline__ void load_kv(const float* __restrict__ Kg,
                                        const float* __restrict__ Vg,
                                        uint32_t kbuf, uint32_t vbuf,
                                        int kv0, int tid) {
#pragma unroll
    for (int t = 0; t < 4; t++) {
        int c = tid + t * 256;
        int r = c >> 4, ch = c & 15;
        cp_async16(kbuf + (uint32_t)(r * 68 + ch * 4) * 4u,
                   Kg + (kv0 + r) * HDIM + ch * 4);
    }
#pragma unroll
    for (int t = 0; t < 4; t++) {
        int c = tid + t * 256;
        int r = c >> 4, ch = c & 15;   // r = d row of V^T, ch = kv chunk
        cp_async16(vbuf + (uint32_t)(r * 68 + ch * 4) * 4u,
                   Vg + r * SEQ + kv0 + ch * 4);
    }
}

__global__ void __launch_bounds__(256) attn_tc()
{
    extern __shared__ char dyn[];
    uint32_t sb = smem_u32(dyn);
    float* smf = (float*)dyn;
    const int tid = threadIdx.x, w = tid >> 5, l = tid & 31;
    const int qb = blockIdx.x, h = blockIdx.y, nb = blockIdx.z;

    const float* Qg = g_Q + ((nb * HEADS + h) * SEQ + qb * 128) * HDIM;
    const float* Kg = g_K + (nb * HEADS + h) * SEQ * HDIM;
    const float* Vg = g_V + (nb * HEADS + h) * HDIM * SEQ;   // [D][L]

    uint32_t sQ = sb, sP = sb + A_OFF_P, sK = sb + A_OFF_K, sV = sb + A_OFF_V;

    load_kv(Kg, Vg, sK, sV, 0, tid);  CP_COMMIT();
    load_kv(Kg, Vg, sK + A_KBUF, sV + A_KBUF, 64, tid);  CP_COMMIT();

    // Q load, scaled by log2(e)/32 (softmax in exp2 domain), re-round to tf32
    const float qscale = 1.4426950408889634f / 32.0f;
#pragma unroll
    for (int t = 0; t < 8; t++) {
        int c = tid + t * 256;
        int r = c >> 4, ch = c & 15;
        float4 v = *(const float4*)(Qg + r * HDIM + ch * 4);
        v.x = tf32r(v.x * qscale); v.y = tf32r(v.y * qscale);
        v.z = tf32r(v.z * qscale); v.w = tf32r(v.w * qscale);
        *(float4*)(smf + r * 68 + ch * 4) = v;
    }

    const int wm = w * 16;
    const uint32_t rowA = (uint32_t)(wm + ((l >> 3) & 1) * 8 + (l & 7));
    const uint32_t colA = (uint32_t)((l >> 4) * 4);
    const uint32_t rowBk = (uint32_t)(l & 7);
    const uint32_t colBk = (uint32_t)(((l >> 3) & 1) * 4);

    float o[8][4] = {};
    float mi0 = -1e30f, mi1 = -1e30f, li0 = 0.f, li1 = 0.f;

    for (int it = 0; it < SEQ / 64; it++) {
        CP_WAIT1();
        __syncthreads();
        if (it + 2 < SEQ / 64) {
            uint32_t po = (uint32_t)((it + 2) % 3) * A_KBUF;
            load_kv(Kg, Vg, sK + po, sV + po, (it + 2) * 64, tid);
        }
        CP_COMMIT();
        uint32_t bo = (uint32_t)(it % 3) * A_KBUF;
        uint32_t kb = sK + bo, vb = sV + bo;

        // ---- S = Q @ K^T (log2-scaled) ----
        float sv[8][4] = {};
#pragma unroll
        for (int ks = 0; ks < 8; ks++) {
            int kk = ks * 8;
            uint32_t a[4];
            ldm_x4(a, sQ + (rowA * 68 + kk + colA) * 4);
#pragma unroll
            for (int nt = 0; nt < 8; nt++) {
                uint32_t b[2];
                ldm_x2(b, kb + ((nt * 8 + rowBk) * 68 + kk + colBk) * 4);
                mma_tf32(sv[nt], a, b);
            }
        }

        // ---- online softmax (exp2 domain) ----
        float rm0 = -1e30f, rm1 = -1e30f;
#pragma unroll
        for (int nt = 0; nt < 8; nt++) {
            rm0 = fmaxf(rm0, fmaxf(sv[nt][0], sv[nt][1]));
            rm1 = fmaxf(rm1, fmaxf(sv[nt][2], sv[nt][3]));
        }
#pragma unroll
        for (int off = 1; off <= 2; off <<= 1) {
            rm0 = fmaxf(rm0, __shfl_xor_sync(0xffffffffu, rm0, off));
            rm1 = fmaxf(rm1, __shfl_xor_sync(0xffffffffu, rm1, off));
        }
        float mn0 = fmaxf(mi0, rm0), mn1 = fmaxf(mi1, rm1);
        float c0 = fexp2(mi0 - mn0), c1 = fexp2(mi1 - mn1);
        float rs0 = 0.f, rs1 = 0.f;
        float* Pp = smf + (A_OFF_P >> 2);
        int pr0 = wm + (l >> 2);
#pragma unroll
        for (int nt = 0; nt < 8; nt++) {
            float p0 = tf32r(fexp2(sv[nt][0] - mn0));
            float p1 = tf32r(fexp2(sv[nt][1] - mn0));
            float p2 = tf32r(fexp2(sv[nt][2] - mn1));
            float p3 = tf32r(fexp2(sv[nt][3] - mn1));
            rs0 += p0 + p1;  rs1 += p2 + p3;
            int cc = nt * 8 + 2 * (l & 3);
            *(float2*)(Pp + pr0 * 68 + cc)       = make_float2(p0, p1);
            *(float2*)(Pp + (pr0 + 8) * 68 + cc) = make_float2(p2, p3);
        }
#pragma unroll
        for (int off = 1; off <= 2; off <<= 1) {
            rs0 += __shfl_xor_sync(0xffffffffu, rs0, off);
            rs1 += __shfl_xor_sync(0xffffffffu, rs1, off);
        }
        li0 = li0 * c0 + rs0;  li1 = li1 * c1 + rs1;
        mi0 = mn0;  mi1 = mn1;
#pragma unroll
        for (int dt = 0; dt < 8; dt++) {
            o[dt][0] *= c0; o[dt][1] *= c0; o[dt][2] *= c1; o[dt][3] *= c1;
        }
        __syncwarp();

        // ---- O += P @ V  (B fragments via ldmatrix on V^T) ----
#pragma unroll
        for (int ks = 0; ks < 8; ks++) {
            int kk = ks * 8;
            uint32_t a[4];
            ldm_x4(a, sP + (rowA * 68 + kk + colA) * 4);
#pragma unroll
            for (int dt = 0; dt < 8; dt++) {
                uint32_t b[2];
                ldm_x2(b, vb + ((dt * 8 + rowBk) * 68 + kk + colBk) * 4);
                mma_tf32(o[dt], a, b);
            }
        }
    }

    // epilogue -> g_AO [N,L,E], tf32-rounded (feeds tf32 proj GEMM)
    float inv0 = 1.f / li0, inv1 = 1.f / li1;
    int r0 = qb * 128 + wm + (l >> 2);
    float* Og = g_AO + (nb * SEQ + r0) * EMBED + h * HDIM;
#pragma unroll
    for (int dt = 0; dt < 8; dt++) {
        int cc = dt * 8 + 2 * (l & 3);
        *(float2*)(Og + cc) =
            make_float2(tf32r(o[dt][0] * inv0), tf32r(o[dt][1] * inv0));
        *(float2*)(Og + 8 * EMBED + cc) =
            make_float2(tf32r(o[dt][2] * inv1), tf32r(o[dt][3] * inv1));
    }
}

// ============================================================================
extern "C" void kernel_launch(void* const* d_in, const int* in_sizes, int n_in,
                              void* d_out, int out_size)
{
    const float* x  = (const float*)d_in[0];
    const float* Wq = (const float*)d_in[1];
    const float* Wk = (const float*)d_in[2];
    const float* Wv = (const float*)d_in[3];
    const float* Wo = (const float*)d_in[4];
    const float* bo = (const float*)d_in[5];
    float* out = (float*)d_out;

    cudaFuncSetAttribute(qkv_tc,  cudaFuncAttributeMaxDynamicSharedMemorySize, G_SMEM);
    cudaFuncSetAttribute(proj_tc, cudaFuncAttributeMaxDynamicSharedMemorySize, G_SMEM);
    cudaFuncSetAttribute(attn_tc, cudaFuncAttributeMaxDynamicSharedMemorySize, A_SMEM);

    dim3 gp(512, 5);
    prep_cvt<<<gp, 256>>>(x, Wq, Wk, Wv, Wo);

    dim3 g1(EMBED / 128, MTOT / 128, 3);
    qkv_tc<<<g1, 256, G_SMEM>>>();

    dim3 g2(SEQ / 128, HEADS, NBATCH);
    attn_tc<<<g2, 256, A_SMEM>>>();

    dim3 g3(EMBED / 128, MTOT / 128);
    proj_tc<<<g3, 256, G_SMEM>>>(bo, out);
}